// round 14
// baseline (speedup 1.0000x reference)
#include <cuda_runtime.h>
#include <cuda_fp16.h>
#include <cstdint>

#define D        128
#define BLK      1024
#define THREADS  256
#define NROWS    262144

// w = ex2(min(S*C2 + ci + cj, 0)), ci = -||xi||^2*log2e/25.6 (pre-scaled in prep)
#define C2       0.11271055f
#define SQSCALE  (-0.056355275f)

// ---- smem: XOR-swizzled tiles. Xi/Xj rows = 256B (16 chunks), W rows = 128B (8 chunks)
#define OFF_XIH  0                     // 64 x 256 = 16K
#define OFF_W    16384                 // 64 x 128 = 8K  (64 j-cols fp16)
#define OFF_XJ   24576                 // 2 buffers x (XjH 16K + XjL 16K)
#define BUF_SZ   32768
#define SM_TOTAL (OFF_XJ + 2 * BUF_SZ) // 90112 -> 2 CTAs/SM

// ---------------- global scratch ----------------
__device__ float   g_sq[NROWS];                     // pre-scaled
__device__ __half  g_xhi[(size_t)NROWS * D];
__device__ __half  g_xlo[(size_t)NROWS * D];

// ---------------- PTX helpers ----------------
__device__ __forceinline__ uint32_t smem_u32(const void* p) {
    uint32_t a;
    asm("{ .reg .u64 t; cvta.to.shared.u64 t, %1; cvt.u32.u64 %0, t; }" : "=r"(a) : "l"(p));
    return a;
}
__device__ __forceinline__ void cpa16(uint32_t dst, const void* src) {
    asm volatile("cp.async.cg.shared.global [%0], [%1], 16;" :: "r"(dst), "l"(src));
}
#define CP_COMMIT() asm volatile("cp.async.commit_group;" ::: "memory")
#define CP_WAIT0()  asm volatile("cp.async.wait_group 0;" ::: "memory")
#define CP_WAIT1()  asm volatile("cp.async.wait_group 1;" ::: "memory")

__device__ __forceinline__ void ldsm4(uint32_t r[4], uint32_t addr) {
    asm volatile("ldmatrix.sync.aligned.m8n8.x4.shared.b16 {%0,%1,%2,%3}, [%4];"
                 : "=r"(r[0]), "=r"(r[1]), "=r"(r[2]), "=r"(r[3]) : "r"(addr));
}
__device__ __forceinline__ void ldsm4t(uint32_t r[4], uint32_t addr) {
    asm volatile("ldmatrix.sync.aligned.m8n8.x4.trans.shared.b16 {%0,%1,%2,%3}, [%4];"
                 : "=r"(r[0]), "=r"(r[1]), "=r"(r[2]), "=r"(r[3]) : "r"(addr));
}
__device__ __forceinline__ void mma16816(float c[4], const uint32_t a[4],
                                         uint32_t b0, uint32_t b1) {
    asm volatile("mma.sync.aligned.m16n8k16.row.col.f32.f16.f16.f32 "
                 "{%0,%1,%2,%3}, {%4,%5,%6,%7}, {%8,%9}, {%0,%1,%2,%3};"
                 : "+f"(c[0]), "+f"(c[1]), "+f"(c[2]), "+f"(c[3])
                 : "r"(a[0]), "r"(a[1]), "r"(a[2]), "r"(a[3]), "r"(b0), "r"(b1));
}
__device__ __forceinline__ float ex2(float e) {
    float r;
    asm("ex2.approx.f32 %0, %1;" : "=f"(r) : "f"(e));
    return r;
}
__device__ __forceinline__ uint32_t h2u(__half2 h) {
    return *reinterpret_cast<uint32_t*>(&h);
}

// ---------------------------------------------------------------------------
// Prepass: fp32 -> fp16 hi/lo + pre-scaled row norms. One warp per row.
// ---------------------------------------------------------------------------
__global__ __launch_bounds__(256) void prep_kernel(const float4* __restrict__ x) {
    int row = blockIdx.x * 8 + (threadIdx.x >> 5);
    int l   = threadIdx.x & 31;
    float4 v = __ldg(&x[(size_t)row * 32 + l]);
    float s = v.x * v.x + v.y * v.y + v.z * v.z + v.w * v.w;
    #pragma unroll
    for (int o = 16; o; o >>= 1) s += __shfl_xor_sync(0xFFFFFFFFu, s, o);
    if (l == 0) g_sq[row] = s * SQSCALE;
    __half2 h01 = __floats2half2_rn(v.x, v.y);
    __half2 h23 = __floats2half2_rn(v.z, v.w);
    float2 f01 = __half22float2(h01);
    float2 f23 = __half22float2(h23);
    __half2 g01 = __floats2half2_rn(v.x - f01.x, v.y - f01.y);
    __half2 g23 = __floats2half2_rn(v.z - f23.x, v.w - f23.y);
    ((uint2*)g_xhi)[(size_t)row * 32 + l] = make_uint2(h2u(h01), h2u(h23));
    ((uint2*)g_xlo)[(size_t)row * 32 + l] = make_uint2(h2u(g01), h2u(g23));
}

// cp.async a 64x128 fp16 tile pair (hi+lo) into swizzled smem (chunk = c16 ^ (row&7))
__device__ __forceinline__ void issue_xj(uint32_t dH, uint32_t dL,
                                         const char* gh, const char* gl, int tid) {
    #pragma unroll
    for (int it = 0; it < 4; ++it) {
        int q   = tid + it * 256;            // 0..1023 16B chunks (64 rows x 16)
        int row = q >> 4, c16 = q & 15;
        uint32_t dsw = (uint32_t)((row << 8) + ((c16 ^ (row & 7)) << 4));
        cpa16(dH + dsw, gh + (size_t)q * 16);
        cpa16(dL + dsw, gl + (size_t)q * 16);
    }
}

// ---------------------------------------------------------------------------
// Fused attention: CTA = 64 i-rows, 2 CTAs/SM; fp16 split;
// 64-row j-tiles, cp.async DOUBLE-buffered (16 iterations).
// Warp grid: wm (0..1) = 32 i-rows; wn (0..3) = 16 j-cols (G1) / 32 d-cols (G2).
// ---------------------------------------------------------------------------
__global__ __launch_bounds__(THREADS, 2)
void attn_kernel(float* __restrict__ out) {
    extern __shared__ char sm[];
    const uint32_t sb = smem_u32(sm);

    const int tid = threadIdx.x;
    const int wid = tid >> 5;
    const int l   = tid & 31;
    const int wm  = wid >> 2;          // 0..1
    const int wn  = wid & 3;           // 0..3
    const int cta  = blockIdx.x;
    const int blkI = cta >> 4, isub = cta & 15;
    const size_t rowbase = (size_t)blkI * BLK;
    const size_t irow0   = rowbase + (size_t)isub * 64;

    const int ph  = l & 7;             // LDSM swizzle phase
    const int rph = (l >> 2) & 7;      // epilogue store phase
    const int cA  = l >> 4;
    const int cB  = (l >> 3) & 1;

    // lane base row offsets
    const uint32_t aRow  = (uint32_t)((32 * wm + (l & 15)) << 8);                  // Xi A-style (256B rows)
    const uint32_t wRowA = (uint32_t)((32 * wm + (l & 15)) << 7);                  // W A-style (128B rows)
    const uint32_t b1Row = (uint32_t)((16 * wn + (l & 7) + ((l >> 4) << 3)) << 8); // G1 B (16 j-rows)
    const uint32_t b2Row = (uint32_t)((l & 15) << 8);                              // G2 B trans (+4096/ks2)

    const char* ghb = (const char*)(g_xhi + rowbase * D);
    const char* glb = (const char*)(g_xlo + rowbase * D);

    // ---- prologue: XiH tile, then Xj tile0 into buf0 ----
    {
        const char* gih = (const char*)(g_xhi + irow0 * D);
        #pragma unroll
        for (int it = 0; it < 4; ++it) {
            int q   = tid + it * 256;
            int row = q >> 4, c16 = q & 15;
            uint32_t dsw = (uint32_t)((row << 8) + ((c16 ^ (row & 7)) << 4));
            cpa16(sb + OFF_XIH + dsw, gih + (size_t)q * 16);
        }
        CP_COMMIT();
    }
    issue_xj(sb + OFF_XJ, sb + OFF_XJ + 16384, ghb, glb, tid);
    CP_COMMIT();

    // pre-scaled i-norms, direct LDG
    float civ[2][2];
    #pragma unroll
    for (int mt = 0; mt < 2; ++mt) {
        civ[mt][0] = __ldg(&g_sq[irow0 + 32 * wm + 16 * mt + (l >> 2)]);
        civ[mt][1] = __ldg(&g_sq[irow0 + 32 * wm + 16 * mt + 8 + (l >> 2)]);
    }

    float acc2[2][4][4];
    #pragma unroll
    for (int mt = 0; mt < 2; ++mt)
        #pragma unroll
        for (int n = 0; n < 4; ++n)
            #pragma unroll
            for (int c = 0; c < 4; ++c) acc2[mt][n][c] = 0.0f;

    for (int jt = 0; jt < 16; ++jt) {
        const uint32_t XJH = sb + OFF_XJ + (uint32_t)(jt & 1) * BUF_SZ;
        const uint32_t XJL = XJH + 16384;

        // prefetch next tile into the other buffer (its readers done at jt-1's end sync)
        if (jt < 15) {
            uint32_t PH = sb + OFF_XJ + (uint32_t)((jt & 1) ^ 1) * BUF_SZ;
            issue_xj(PH, PH + 16384,
                     ghb + (size_t)(jt + 1) * 16384, glb + (size_t)(jt + 1) * 16384, tid);
            CP_COMMIT();
            CP_WAIT1();    // current tile (and Xi) landed; prefetch may fly
        } else {
            CP_WAIT0();
        }
        __syncthreads();   // Xj(jt) visible to all

        // ---- GEMM1: S(32x16/warp) = XiH . XjH^T (1 combo) ----
        float acc1[2][2][4];
        #pragma unroll
        for (int mt = 0; mt < 2; ++mt)
            #pragma unroll
            for (int n = 0; n < 2; ++n)
                #pragma unroll
                for (int c = 0; c < 4; ++c) acc1[mt][n][c] = 0.0f;

        #pragma unroll
        for (int ks = 0; ks < 8; ++ks) {
            const uint32_t ca = (uint32_t)(((2 * ks + cA) ^ ph) << 4);
            const uint32_t cb = (uint32_t)(((2 * ks + cB) ^ ph) << 4);
            uint32_t ah[2][4];
            #pragma unroll
            for (int mt = 0; mt < 2; ++mt)
                ldsm4(ah[mt], sb + OFF_XIH + aRow + mt * 4096 + ca);
            uint32_t bh[4];
            ldsm4(bh, XJH + b1Row + cb);
            #pragma unroll
            for (int mt = 0; mt < 2; ++mt) {
                mma16816(acc1[mt][0], ah[mt], bh[0], bh[1]);
                mma16816(acc1[mt][1], ah[mt], bh[2], bh[3]);
            }
        }

        // ---- epilogue: w -> swizzled W tile (64 rows x 64 j, 128B rows) ----
        {
            const float2* cjp = (const float2*)(g_sq + rowbase + (size_t)jt * 64);
            #pragma unroll
            for (int n = 0; n < 2; ++n) {
                float2 cj = __ldg(&cjp[8 * wn + 4 * n + (l & 3)]);
                const uint32_t wcol = (uint32_t)((((2 * wn + n) ^ rph) << 4) + ((l & 3) << 2));
                #pragma unroll
                for (int mt = 0; mt < 2; ++mt) {
                    const float* c = acc1[mt][n];
                    float w0 = ex2(fminf(fmaf(c[0], C2, civ[mt][0] + cj.x), 0.0f));
                    float w1 = ex2(fminf(fmaf(c[1], C2, civ[mt][0] + cj.y), 0.0f));
                    float w2 = ex2(fminf(fmaf(c[2], C2, civ[mt][1] + cj.x), 0.0f));
                    float w3 = ex2(fminf(fmaf(c[3], C2, civ[mt][1] + cj.y), 0.0f));
                    const uint32_t wr = (uint32_t)((32 * wm + 16 * mt + (l >> 2)) << 7);
                    *(uint32_t*)(sm + OFF_W + wr + wcol)        = h2u(__floats2half2_rn(w0, w1));
                    *(uint32_t*)(sm + OFF_W + wr + 1024 + wcol) = h2u(__floats2half2_rn(w2, w3));
                }
            }
        }
        __syncthreads();   // W complete

        // ---- GEMM2: acc2(32x32/warp) += W . Xj  (2 combos, K=64) ----
        #pragma unroll
        for (int ks2 = 0; ks2 < 4; ++ks2) {
            const uint32_t ca = (uint32_t)(((2 * ks2 + cA) ^ ph) << 4);
            uint32_t wh[2][4];
            #pragma unroll
            for (int mt = 0; mt < 2; ++mt)
                ldsm4(wh[mt], sb + OFF_W + wRowA + mt * 2048 + ca);
            #pragma unroll
            for (int dp = 0; dp < 2; ++dp) {
                const uint32_t cb2 = (uint32_t)(((4 * wn + 2 * dp + cA) ^ ph) << 4);
                uint32_t bh[4], bl[4];
                ldsm4t(bh, XJH + b2Row + ks2 * 4096 + cb2);
                ldsm4t(bl, XJL + b2Row + ks2 * 4096 + cb2);
                #pragma unroll
                for (int mt = 0; mt < 2; ++mt) {
                    mma16816(acc2[mt][2 * dp],     wh[mt], bh[0], bh[1]);
                    mma16816(acc2[mt][2 * dp + 1], wh[mt], bh[2], bh[3]);
                    mma16816(acc2[mt][2 * dp],     wh[mt], bl[0], bl[1]);
                    mma16816(acc2[mt][2 * dp + 1], wh[mt], bl[2], bl[3]);
                }
            }
        }

        __syncthreads();   // Xj + W readers done -> prefetch target / W writable
    }

    // ---- write out (scale 1/1024) ----
    const float sc = 1.0f / (float)BLK;
    #pragma unroll
    for (int mt = 0; mt < 2; ++mt) {
        const size_t r0 = irow0 + 32 * wm + 16 * mt + (l >> 2);
        #pragma unroll
        for (int n = 0; n < 4; ++n) {
            const int col = 32 * wn + 8 * n + 2 * (l & 3);
            *(float2*)(out + r0 * D + col)       = make_float2(acc2[mt][n][0] * sc, acc2[mt][n][1] * sc);
            *(float2*)(out + (r0 + 8) * D + col) = make_float2(acc2[mt][n][2] * sc, acc2[mt][n][3] * sc);
        }
    }
}

// ---------------------------------------------------------------------------
extern "C" void kernel_launch(void* const* d_in, const int* in_sizes, int n_in,
                              void* d_out, int out_size) {
    const float* x = (const float*)d_in[0];
    float* out = (float*)d_out;
    const int nrows = in_sizes[0] / D;

    static bool attr_set = false;
    if (!attr_set) {
        cudaFuncSetAttribute(attn_kernel,
                             cudaFuncAttributeMaxDynamicSharedMemorySize, SM_TOTAL);
        attr_set = true;
    }
    prep_kernel<<<nrows / 8, 256>>>((const float4*)x);
    attn_kernel<<<nrows / 64, THREADS, SM_TOTAL>>>(out);
}

// round 15
// speedup vs baseline: 1.4536x; 1.4536x over previous
#include <cuda_runtime.h>
#include <cuda_fp16.h>
#include <cstdint>

#define D        128
#define BLK      1024
#define THREADS  256
#define NROWS    262144

// w = ex2(min(S*C2 + ci + cj, 0)), ci = -||xi||^2*log2e/25.6 (pre-scaled in prep)
#define C2       0.11271055f
#define SQSCALE  (-0.056355275f)

// ---- smem: XOR-swizzled 256B-row tiles ----
#define OFF_XIH  0                     // 64 x 256 = 16K
#define OFF_W    16384                 // 64 x 256 = 16K (128 j-cols fp16)
#define OFF_XJ   32768                 // 2 x XjH (128 x 256 = 32K each)
#define BUF_SZ   32768
#define SM_TOTAL (OFF_XJ + 2 * BUF_SZ) // 98304 -> 2 CTAs/SM

// ---------------- global scratch ----------------
__device__ float   g_sq[NROWS];                     // pre-scaled
__device__ __half  g_xhi[(size_t)NROWS * D];

// ---------------- PTX helpers ----------------
__device__ __forceinline__ uint32_t smem_u32(const void* p) {
    uint32_t a;
    asm("{ .reg .u64 t; cvta.to.shared.u64 t, %1; cvt.u32.u64 %0, t; }" : "=r"(a) : "l"(p));
    return a;
}
__device__ __forceinline__ void cpa16(uint32_t dst, const void* src) {
    asm volatile("cp.async.cg.shared.global [%0], [%1], 16;" :: "r"(dst), "l"(src));
}
#define CP_COMMIT() asm volatile("cp.async.commit_group;" ::: "memory")
#define CP_WAIT0()  asm volatile("cp.async.wait_group 0;" ::: "memory")

__device__ __forceinline__ void ldsm4(uint32_t r[4], uint32_t addr) {
    asm volatile("ldmatrix.sync.aligned.m8n8.x4.shared.b16 {%0,%1,%2,%3}, [%4];"
                 : "=r"(r[0]), "=r"(r[1]), "=r"(r[2]), "=r"(r[3]) : "r"(addr));
}
__device__ __forceinline__ void ldsm4t(uint32_t r[4], uint32_t addr) {
    asm volatile("ldmatrix.sync.aligned.m8n8.x4.trans.shared.b16 {%0,%1,%2,%3}, [%4];"
                 : "=r"(r[0]), "=r"(r[1]), "=r"(r[2]), "=r"(r[3]) : "r"(addr));
}
__device__ __forceinline__ void mma16816(float c[4], const uint32_t a[4],
                                         uint32_t b0, uint32_t b1) {
    asm volatile("mma.sync.aligned.m16n8k16.row.col.f32.f16.f16.f32 "
                 "{%0,%1,%2,%3}, {%4,%5,%6,%7}, {%8,%9}, {%0,%1,%2,%3};"
                 : "+f"(c[0]), "+f"(c[1]), "+f"(c[2]), "+f"(c[3])
                 : "r"(a[0]), "r"(a[1]), "r"(a[2]), "r"(a[3]), "r"(b0), "r"(b1));
}
__device__ __forceinline__ float ex2(float e) {
    float r;
    asm("ex2.approx.f32 %0, %1;" : "=f"(r) : "f"(e));
    return r;
}
__device__ __forceinline__ uint32_t h2u(__half2 h) {
    return *reinterpret_cast<uint32_t*>(&h);
}

// ---------------------------------------------------------------------------
// Prepass: fp32 -> fp16 (hi only) + pre-scaled row norms. One warp per row.
// ---------------------------------------------------------------------------
__global__ __launch_bounds__(256) void prep_kernel(const float4* __restrict__ x) {
    int row = blockIdx.x * 8 + (threadIdx.x >> 5);
    int l   = threadIdx.x & 31;
    float4 v = __ldg(&x[(size_t)row * 32 + l]);
    float s = v.x * v.x + v.y * v.y + v.z * v.z + v.w * v.w;
    #pragma unroll
    for (int o = 16; o; o >>= 1) s += __shfl_xor_sync(0xFFFFFFFFu, s, o);
    if (l == 0) g_sq[row] = s * SQSCALE;
    __half2 h01 = __floats2half2_rn(v.x, v.y);
    __half2 h23 = __floats2half2_rn(v.z, v.w);
    ((uint2*)g_xhi)[(size_t)row * 32 + l] = make_uint2(h2u(h01), h2u(h23));
}

// cp.async a 128x128 fp16 tile into swizzled smem (chunk = c16 ^ (row&7))
__device__ __forceinline__ void issue_xj(uint32_t dH, const char* gh, int tid) {
    #pragma unroll
    for (int it = 0; it < 8; ++it) {
        int q   = tid + it * 256;            // 0..2047 16B chunks
        int row = q >> 4, c16 = q & 15;
        uint32_t dsw = (uint32_t)((row << 8) + ((c16 ^ (row & 7)) << 4));
        cpa16(dH + dsw, gh + (size_t)q * 16);
    }
}

// ---------------------------------------------------------------------------
// Fused attention: CTA = 64 i-rows, 2 CTAs/SM; fp16; 128-j tiles,
// cp.async double-buffered. GEMM1 = 1 combo; GEMM2 = W.XjH (1 combo).
// Warp grid: wm (0..1) = 32 i-rows; wn (0..3) = 32 j-cols (G1) / 32 d-cols (G2).
// ---------------------------------------------------------------------------
__global__ __launch_bounds__(THREADS, 2)
void attn_kernel(float* __restrict__ out) {
    extern __shared__ char sm[];
    const uint32_t sb = smem_u32(sm);

    const int tid = threadIdx.x;
    const int wid = tid >> 5;
    const int l   = tid & 31;
    const int wm  = wid >> 2;          // 0..1
    const int wn  = wid & 3;           // 0..3
    const int cta  = blockIdx.x;
    const int blkI = cta >> 4, isub = cta & 15;
    const size_t rowbase = (size_t)blkI * BLK;
    const size_t irow0   = rowbase + (size_t)isub * 64;

    const int ph  = l & 7;             // LDSM swizzle phase
    const int rph = (l >> 2) & 7;      // epilogue store phase
    const int cA  = l >> 4;
    const int cB  = (l >> 3) & 1;

    const uint32_t aRow  = (uint32_t)((32 * wm + (l & 15)) << 8);                  // Xi / W A-style
    const uint32_t b1Row = (uint32_t)((32 * wn + (l & 7) + ((l >> 4) << 3)) << 8); // G1 B (+4096/nt2)
    const uint32_t b2Row = (uint32_t)((l & 15) << 8);                              // G2 B trans (+4096/ks)

    const char* ghb = (const char*)(g_xhi + rowbase * D);

    // ---- prologue: XiH tile + Xj0 into buf0 ----
    {
        const char* gih = (const char*)(g_xhi + irow0 * D);
        #pragma unroll
        for (int it = 0; it < 4; ++it) {
            int q   = tid + it * 256;
            int row = q >> 4, c16 = q & 15;
            uint32_t dsw = (uint32_t)((row << 8) + ((c16 ^ (row & 7)) << 4));
            cpa16(sb + OFF_XIH + dsw, gih + (size_t)q * 16);
        }
    }
    issue_xj(sb + OFF_XJ, ghb, tid);
    CP_COMMIT();

    // pre-scaled i-norms, direct LDG
    float civ[2][2];
    #pragma unroll
    for (int mt = 0; mt < 2; ++mt) {
        civ[mt][0] = __ldg(&g_sq[irow0 + 32 * wm + 16 * mt + (l >> 2)]);
        civ[mt][1] = __ldg(&g_sq[irow0 + 32 * wm + 16 * mt + 8 + (l >> 2)]);
    }

    float acc2[2][4][4];
    #pragma unroll
    for (int mt = 0; mt < 2; ++mt)
        #pragma unroll
        for (int n = 0; n < 4; ++n)
            #pragma unroll
            for (int c = 0; c < 4; ++c) acc2[mt][n][c] = 0.0f;

    CP_WAIT0();
    __syncthreads();

    for (int jt = 0; jt < 8; ++jt) {
        const uint32_t XJH = sb + OFF_XJ + (uint32_t)(jt & 1) * BUF_SZ;

        // prefetch next tile into the other buffer (readers done at jt-1's bottom sync)
        if (jt < 7) {
            issue_xj(sb + OFF_XJ + (uint32_t)((jt & 1) ^ 1) * BUF_SZ,
                     ghb + (size_t)(jt + 1) * 32768, tid);
            CP_COMMIT();
        }

        // ---- GEMM1: S(32x32/warp) = XiH . XjH^T (1 combo) ----
        float acc1[2][4][4];
        #pragma unroll
        for (int mt = 0; mt < 2; ++mt)
            #pragma unroll
            for (int n = 0; n < 4; ++n)
                #pragma unroll
                for (int c = 0; c < 4; ++c) acc1[mt][n][c] = 0.0f;

        #pragma unroll
        for (int ks = 0; ks < 8; ++ks) {
            const uint32_t ca = (uint32_t)(((2 * ks + cA) ^ ph) << 4);
            const uint32_t cb = (uint32_t)(((2 * ks + cB) ^ ph) << 4);
            uint32_t ah[2][4];
            #pragma unroll
            for (int mt = 0; mt < 2; ++mt)
                ldsm4(ah[mt], sb + OFF_XIH + aRow + mt * 4096 + ca);
            #pragma unroll
            for (int nt2 = 0; nt2 < 2; ++nt2) {
                uint32_t bh[4];
                ldsm4(bh, XJH + b1Row + nt2 * 4096 + cb);
                #pragma unroll
                for (int mt = 0; mt < 2; ++mt) {
                    mma16816(acc1[mt][2 * nt2],     ah[mt], bh[0], bh[1]);
                    mma16816(acc1[mt][2 * nt2 + 1], ah[mt], bh[2], bh[3]);
                }
            }
        }

        // ---- epilogue: w -> swizzled W tile (64 x 128 fp16) ----
        {
            const float2* cjp = (const float2*)(g_sq + rowbase + (size_t)jt * 128);
            #pragma unroll
            for (int n = 0; n < 4; ++n) {
                float2 cj = __ldg(&cjp[16 * wn + 4 * n + (l & 3)]);
                const uint32_t wcol = (uint32_t)((((4 * wn + n) ^ rph) << 4) + ((l & 3) << 2));
                #pragma unroll
                for (int mt = 0; mt < 2; ++mt) {
                    const float* c = acc1[mt][n];
                    float w0 = ex2(fminf(fmaf(c[0], C2, civ[mt][0] + cj.x), 0.0f));
                    float w1 = ex2(fminf(fmaf(c[1], C2, civ[mt][0] + cj.y), 0.0f));
                    float w2 = ex2(fminf(fmaf(c[2], C2, civ[mt][1] + cj.x), 0.0f));
                    float w3 = ex2(fminf(fmaf(c[3], C2, civ[mt][1] + cj.y), 0.0f));
                    const uint32_t wr = (uint32_t)((32 * wm + 16 * mt + (l >> 2)) << 8);
                    *(uint32_t*)(sm + OFF_W + wr + wcol)        = h2u(__floats2half2_rn(w0, w1));
                    *(uint32_t*)(sm + OFF_W + wr + 2048 + wcol) = h2u(__floats2half2_rn(w2, w3));
                }
            }
        }
        __syncthreads();   // W complete

        // ---- GEMM2: acc2(32x32/warp) += W . XjH  (1 combo, K=128) ----
        #pragma unroll
        for (int ks = 0; ks < 8; ++ks) {
            const uint32_t ca = (uint32_t)(((2 * ks + cA) ^ ph) << 4);
            uint32_t wh[2][4];
            #pragma unroll
            for (int mt = 0; mt < 2; ++mt)
                ldsm4(wh[mt], sb + OFF_W + aRow + mt * 4096 + ca);
            #pragma unroll
            for (int dp = 0; dp < 2; ++dp) {
                const uint32_t cb2 = (uint32_t)(((4 * wn + 2 * dp + cA) ^ ph) << 4);
                uint32_t bh[4];
                ldsm4t(bh, XJH + b2Row + ks * 4096 + cb2);
                #pragma unroll
                for (int mt = 0; mt < 2; ++mt) {
                    mma16816(acc2[mt][2 * dp],     wh[mt], bh[0], bh[1]);
                    mma16816(acc2[mt][2 * dp + 1], wh[mt], bh[2], bh[3]);
                }
            }
        }

        CP_WAIT0();        // next buffer landed
        __syncthreads();   // readers done; W + prefetch target writable
    }

    // ---- write out (scale 1/1024) ----
    const float sc = 1.0f / (float)BLK;
    #pragma unroll
    for (int mt = 0; mt < 2; ++mt) {
        const size_t r0 = irow0 + 32 * wm + 16 * mt + (l >> 2);
        #pragma unroll
        for (int n = 0; n < 4; ++n) {
            const int col = 32 * wn + 8 * n + 2 * (l & 3);
            *(float2*)(out + r0 * D + col)       = make_float2(acc2[mt][n][0] * sc, acc2[mt][n][1] * sc);
            *(float2*)(out + (r0 + 8) * D + col) = make_float2(acc2[mt][n][2] * sc, acc2[mt][n][3] * sc);
        }
    }
}

// ---------------------------------------------------------------------------
extern "C" void kernel_launch(void* const* d_in, const int* in_sizes, int n_in,
                              void* d_out, int out_size) {
    const float* x = (const float*)d_in[0];
    float* out = (float*)d_out;
    const int nrows = in_sizes[0] / D;

    static bool attr_set = false;
    if (!attr_set) {
        cudaFuncSetAttribute(attn_kernel,
                             cudaFuncAttributeMaxDynamicSharedMemorySize, SM_TOTAL);
        attr_set = true;
    }
    prep_kernel<<<nrows / 8, 256>>>((const float4*)x);
    attn_kernel<<<nrows / 64, THREADS, SM_TOTAL>>>(out);
}